// round 8
// baseline (speedup 1.0000x reference)
#include <cuda_runtime.h>
#include <math_constants.h>

// contributions: [S=256, P=2000, C=200] fp32, row-major (c contiguous).
// Per (s, c) column along P: zero the top-4 (stable ties -> lower p), pass rest.
//
// R7: float4 (LDG.128/STG.128) to beat the LSU issue-cost wall (STG.32 = 5cyc
// per 128B vs STG.128 = 12cyc per 512B), combined with the batched max-reject
// so the compute side stays lean (R3's failure was per-element branches).
// One thread = 4 adjacent columns x 1/16th of P. 204800 threads.

static constexpr int S = 256;
static constexpr int P = 2000;
static constexpr int C = 200;
static constexpr int NCOL = S * C;            // 51200
static constexpr int VEC  = 4;
static constexpr int NGRP = NCOL / VEC;       // 12800 float4-column groups
static constexpr int GPS  = C / VEC;          // 50 float4s per row
static constexpr int SEG  = 16;               // P-segments per column
static constexpr int PSEG = P / SEG;          // 125 rows per segment
static constexpr int U    = 5;                // 125 = 25 * 5
static constexpr int NB   = PSEG / U;         // 25 batches
static constexpr int G    = 8;                // groups per block
static constexpr int BLK  = G * SEG;          // 128 threads
static constexpr int GRID = NGRP / G;         // 1600 blocks
static constexpr int CPB  = G * VEC;          // 32 columns per block

__device__ __forceinline__ void ins4(float (&t)[4], int (&ix)[4], float v, int p) {
    // strict > : earlier p wins ties (stable argsort semantics)
    if (v > t[3]) {
        if (v > t[0]) {
            t[3]=t[2]; ix[3]=ix[2]; t[2]=t[1]; ix[2]=ix[1]; t[1]=t[0]; ix[1]=ix[0];
            t[0]=v; ix[0]=p;
        } else if (v > t[1]) {
            t[3]=t[2]; ix[3]=ix[2]; t[2]=t[1]; ix[2]=ix[1];
            t[1]=v; ix[1]=p;
        } else if (v > t[2]) {
            t[3]=t[2]; ix[3]=ix[2];
            t[2]=v; ix[2]=p;
        } else {
            t[3]=v; ix[3]=p;
        }
    }
}

__global__ void __launch_bounds__(BLK)
numproto_topk_zero(const float* __restrict__ in, float* __restrict__ out) {
    const int tid = threadIdx.x;
    const int seg = tid >> 3;                 // 0..15
    const int gi  = tid & 7;                  // 0..7
    const int g   = blockIdx.x * G + gi;      // float4-group id

    const int s  = g / GPS;
    const int cg = g - s * GPS;

    const int p0 = seg * PSEG;
    const float4* __restrict__ ipp =
        (const float4*)(in  + (size_t)s * P * C) + cg + (size_t)p0 * GPS;
    float4* __restrict__ opp =
        (float4*)      (out + (size_t)s * P * C) + cg + (size_t)p0 * GPS;

    float t[VEC][4];
    int   ix[VEC][4];
    #pragma unroll
    for (int j = 0; j < VEC; j++) {
        #pragma unroll
        for (int r = 0; r < 4; r++) { t[j][r] = -CUDART_INF_F; ix[j][r] = 0; }
    }

    int pbase = p0;
    for (int it = 0; it < NB; it++) {
        float4 v[U];
        #pragma unroll
        for (int u = 0; u < U; u++)
            v[u] = ipp[u * GPS];              // immediate offsets (u*800B)
        #pragma unroll
        for (int u = 0; u < U; u++)
            opp[u * GPS] = v[u];

        // per-column max of the 5-element batch (4 fmaxf per column)
        float mxx = fmaxf(fmaxf(fmaxf(v[0].x, v[1].x), fmaxf(v[2].x, v[3].x)), v[4].x);
        float mxy = fmaxf(fmaxf(fmaxf(v[0].y, v[1].y), fmaxf(v[2].y, v[3].y)), v[4].y);
        float mxz = fmaxf(fmaxf(fmaxf(v[0].z, v[1].z), fmaxf(v[2].z, v[3].z)), v[4].z);
        float mxw = fmaxf(fmaxf(fmaxf(v[0].w, v[1].w), fmaxf(v[2].w, v[3].w)), v[4].w);

        if (mxx > t[0][3]) {
            #pragma unroll
            for (int u = 0; u < U; u++) ins4(t[0], ix[0], v[u].x, pbase + u);
        }
        if (mxy > t[1][3]) {
            #pragma unroll
            for (int u = 0; u < U; u++) ins4(t[1], ix[1], v[u].y, pbase + u);
        }
        if (mxz > t[2][3]) {
            #pragma unroll
            for (int u = 0; u < U; u++) ins4(t[2], ix[2], v[u].z, pbase + u);
        }
        if (mxw > t[3][3]) {
            #pragma unroll
            for (int u = 0; u < U; u++) ins4(t[3], ix[3], v[u].w, pbase + u);
        }

        ipp += U * GPS;
        opp += U * GPS;
        pbase += U;
    }

    // exchange: [seg][rank][col]; conflict-free in both phases
    __shared__ float sv[SEG][4][CPB];
    __shared__ int   si[SEG][4][CPB];
    #pragma unroll
    for (int j = 0; j < VEC; j++) {
        const int colL = gi * VEC + j;
        #pragma unroll
        for (int r = 0; r < 4; r++) {
            sv[seg][r][colL] = t[j][r];
            si[seg][r][colL] = ix[j][r];
        }
    }

    __syncthreads();   // orders this block's copy-stores before the patch

    if (tid < CPB) {
        const int col = blockIdx.x * CPB + tid;
        const int ps  = col / C;
        const int pc  = col - ps * C;
        float* opc = out + (size_t)ps * P * C + pc;

        float m[4] = {-CUDART_INF_F, -CUDART_INF_F, -CUDART_INF_F, -CUDART_INF_F};
        int   jx[4] = {0x7fffffff, 0x7fffffff, 0x7fffffff, 0x7fffffff};
        #pragma unroll
        for (int sg = 0; sg < SEG; sg++) {
            #pragma unroll
            for (int k = 0; k < 4; k++) {
                float v = sv[sg][k][tid];
                int   i = si[sg][k][tid];
                if (v > m[3] || (v == m[3] && i < jx[3])) {
                    if (v > m[0] || (v == m[0] && i < jx[0])) {
                        m[3]=m[2]; jx[3]=jx[2]; m[2]=m[1]; jx[2]=jx[1];
                        m[1]=m[0]; jx[1]=jx[0]; m[0]=v; jx[0]=i;
                    } else if (v > m[1] || (v == m[1] && i < jx[1])) {
                        m[3]=m[2]; jx[3]=jx[2]; m[2]=m[1]; jx[2]=jx[1];
                        m[1]=v; jx[1]=i;
                    } else if (v > m[2] || (v == m[2] && i < jx[2])) {
                        m[3]=m[2]; jx[3]=jx[2];
                        m[2]=v; jx[2]=i;
                    } else {
                        m[3]=v; jx[3]=i;
                    }
                }
            }
        }
        opc[(size_t)jx[0] * C] = 0.0f;
        opc[(size_t)jx[1] * C] = 0.0f;
        opc[(size_t)jx[2] * C] = 0.0f;
        opc[(size_t)jx[3] * C] = 0.0f;
    }
}

extern "C" void kernel_launch(void* const* d_in, const int* in_sizes, int n_in,
                              void* d_out, int out_size) {
    (void)in_sizes; (void)n_in; (void)out_size;
    const float* in  = (const float*)d_in[0];
    float*       out = (float*)d_out;
    numproto_topk_zero<<<GRID, BLK>>>(in, out);
}

// round 9
// speedup vs baseline: 1.0936x; 1.0936x over previous
#include <cuda_runtime.h>
#include <math_constants.h>

// contributions: [S=256, P=2000, C=200] fp32, row-major (c contiguous).
// Per (s, c) column along P: zero the top-4 (stable ties -> lower p), pass rest.
//
// R8: R5 per-thread code exactly (1 col/thread segment, batched max-reject,
// immediate-offset addressing, ~36 regs) but SEG=8 / COLS=16 / BLK=128 /
// GRID=3200: 12800 warps, residency ~56 warps/SM (reg-limited), ~6 fine
// waves for smooth work-steal. Attacks the measured warps->BW scaling curve.

static constexpr int S = 256;
static constexpr int P = 2000;
static constexpr int C = 200;
static constexpr int NCOL = S * C;          // 51200 columns
static constexpr int SEG  = 8;              // segments per column
static constexpr int PSEG = P / SEG;        // 250
static constexpr int U    = 10;             // 250 = 25 * 10
static constexpr int NB   = PSEG / U;       // 25 batches
static constexpr int COLS = 16;             // columns per block
static constexpr int BLK  = COLS * SEG;     // 128 threads
static constexpr int GRID = NCOL / COLS;    // 3200 blocks

__global__ void __launch_bounds__(BLK)
numproto_topk_zero(const float* __restrict__ in, float* __restrict__ out) {
    const int tid  = threadIdx.x;
    const int seg  = tid / COLS;            // 0..7
    const int lane = tid % COLS;            // 0..15 (16 consecutive columns)
    const int col  = blockIdx.x * COLS + lane;

    const int s = col / C;
    const int c = col - s * C;

    const int p0 = seg * PSEG;
    const float* __restrict__ ipp = in  + (size_t)s * P * C + c + (size_t)p0 * C;
    float*       __restrict__ opp = out + (size_t)s * P * C + c + (size_t)p0 * C;

    float t0 = -CUDART_INF_F, t1 = -CUDART_INF_F,
          t2 = -CUDART_INF_F, t3 = -CUDART_INF_F;
    int   i0 = 0, i1 = 0, i2 = 0, i3 = 0;

    int pbase = p0;
    for (int it = 0; it < NB; it++) {
        float v[U];
        #pragma unroll
        for (int u = 0; u < U; u++)
            v[u] = ipp[u * C];              // immediate offsets
        #pragma unroll
        for (int u = 0; u < U; u++)
            opp[u * C] = v[u];

        // batched rejection: one branch per 10 elements
        float m01 = fmaxf(v[0], v[1]);
        float m23 = fmaxf(v[2], v[3]);
        float m45 = fmaxf(v[4], v[5]);
        float m67 = fmaxf(v[6], v[7]);
        float m89 = fmaxf(v[8], v[9]);
        float mx  = fmaxf(fmaxf(fmaxf(m01, m23), fmaxf(m45, m67)), m89);

        if (mx > t3) {  // rare after warm-up
            #pragma unroll
            for (int u = 0; u < U; u++) {
                float vv = v[u];
                if (vv > t3) {
                    int pp = pbase + u;
                    if (vv > t0) {
                        t3 = t2; i3 = i2; t2 = t1; i2 = i1; t1 = t0; i1 = i0;
                        t0 = vv; i0 = pp;
                    } else if (vv > t1) {
                        t3 = t2; i3 = i2; t2 = t1; i2 = i1;
                        t1 = vv; i1 = pp;
                    } else if (vv > t2) {
                        t3 = t2; i3 = i2;
                        t2 = vv; i2 = pp;
                    } else {
                        t3 = vv; i3 = pp;
                    }
                }
            }
        }
        ipp += U * C;
        opp += U * C;
        pbase += U;
    }

    // candidate exchange: [seg][rank][col] -> conflict-free both phases
    __shared__ float sv[SEG][4][COLS];
    __shared__ int   si[SEG][4][COLS];
    sv[seg][0][lane] = t0; si[seg][0][lane] = i0;
    sv[seg][1][lane] = t1; si[seg][1][lane] = i1;
    sv[seg][2][lane] = t2; si[seg][2][lane] = i2;
    sv[seg][3][lane] = t3; si[seg][3][lane] = i3;

    __syncthreads();   // also orders this block's copy-stores before the patch

    if (tid < COLS) {
        const int pcol = blockIdx.x * COLS + tid;
        const int ps   = pcol / C;
        const int pc   = pcol - ps * C;
        float* opc = out + (size_t)ps * P * C + pc;

        float m0 = -CUDART_INF_F, m1 = -CUDART_INF_F,
              m2 = -CUDART_INF_F, m3 = -CUDART_INF_F;
        int   j0 = 0x7fffffff, j1 = 0x7fffffff,
              j2 = 0x7fffffff, j3 = 0x7fffffff;
        #pragma unroll
        for (int sg = 0; sg < SEG; sg++) {
            #pragma unroll
            for (int k = 0; k < 4; k++) {
                float v = sv[sg][k][tid];
                int   i = si[sg][k][tid];
                if (v > m3 || (v == m3 && i < j3)) {
                    if (v > m0 || (v == m0 && i < j0)) {
                        m3 = m2; j3 = j2; m2 = m1; j2 = j1; m1 = m0; j1 = j0;
                        m0 = v;  j0 = i;
                    } else if (v > m1 || (v == m1 && i < j1)) {
                        m3 = m2; j3 = j2; m2 = m1; j2 = j1;
                        m1 = v;  j1 = i;
                    } else if (v > m2 || (v == m2 && i < j2)) {
                        m3 = m2; j3 = j2;
                        m2 = v;  j2 = i;
                    } else {
                        m3 = v;  j3 = i;
                    }
                }
            }
        }
        opc[(size_t)j0 * C] = 0.0f;
        opc[(size_t)j1 * C] = 0.0f;
        opc[(size_t)j2 * C] = 0.0f;
        opc[(size_t)j3 * C] = 0.0f;
    }
}

extern "C" void kernel_launch(void* const* d_in, const int* in_sizes, int n_in,
                              void* d_out, int out_size) {
    (void)in_sizes; (void)n_in; (void)out_size;
    const float* in  = (const float*)d_in[0];
    float*       out = (float*)d_out;
    numproto_topk_zero<<<GRID, BLK>>>(in, out);
}

// round 10
// speedup vs baseline: 1.1940x; 1.0918x over previous
#include <cuda_runtime.h>
#include <math_constants.h>

// contributions: [S=256, P=2000, C=200] fp32, row-major (c contiguous).
// Per (s, c) column along P: zero the top-4 (stable ties -> lower p), pass rest.
//
// R9: R5 structure (SEG=4, COLS=32, BLK=128, GRID=1600, ~43 warps/SM,
// batched max-reject, immediate-offset addressing) but the top-4 insert is a
// SHORT BRANCHLESS select chain guarded per element -- kills the divergent
// nested if-else serialization that was costing ~28 issued instr/element.

static constexpr int S = 256;
static constexpr int P = 2000;
static constexpr int C = 200;
static constexpr int NCOL = S * C;          // 51200 columns
static constexpr int SEG  = 4;              // segments (warps) per column group
static constexpr int PSEG = P / SEG;        // 500
static constexpr int U    = 10;             // 500 = 50 * 10
static constexpr int NB   = PSEG / U;       // 50 batches
static constexpr int COLS = 32;             // columns per block (full warp)
static constexpr int BLK  = COLS * SEG;     // 128 threads
static constexpr int GRID = NCOL / COLS;    // 1600 blocks

__global__ void __launch_bounds__(BLK)
numproto_topk_zero(const float* __restrict__ in, float* __restrict__ out) {
    const int tid  = threadIdx.x;
    const int seg  = tid >> 5;              // 0..3
    const int lane = tid & 31;              // 32 consecutive columns per warp
    const int col  = blockIdx.x * COLS + lane;

    const int s = col / C;
    const int c = col - s * C;

    const int p0 = seg * PSEG;
    const float* __restrict__ ipp = in  + (size_t)s * P * C + c + (size_t)p0 * C;
    float*       __restrict__ opp = out + (size_t)s * P * C + c + (size_t)p0 * C;

    float t0 = -CUDART_INF_F, t1 = -CUDART_INF_F,
          t2 = -CUDART_INF_F, t3 = -CUDART_INF_F;
    int   i0 = 0, i1 = 0, i2 = 0, i3 = 0;

    int pbase = p0;
    for (int it = 0; it < NB; it++) {
        float v[U];
        #pragma unroll
        for (int u = 0; u < U; u++)
            v[u] = ipp[u * C];              // immediate offsets
        #pragma unroll
        for (int u = 0; u < U; u++)
            opp[u * C] = v[u];

        // batch screen: one branch per 10 elements (skips whole batch late)
        float m01 = fmaxf(v[0], v[1]);
        float m23 = fmaxf(v[2], v[3]);
        float m45 = fmaxf(v[4], v[5]);
        float m67 = fmaxf(v[6], v[7]);
        float m89 = fmaxf(v[8], v[9]);
        float mx  = fmaxf(fmaxf(fmaxf(m01, m23), fmaxf(m45, m67)), m89);

        if (mx > t3) {
            #pragma unroll
            for (int u = 0; u < U; u++) {
                float vv = v[u];
                if (vv > t3) {              // short single-path branchless insert
                    const int pp = pbase + u;
                    const bool c0 = vv > t0;
                    const bool c1 = vv > t1;
                    const bool c2 = vv > t2;
                    float nt0 = c0 ? vv : t0;           int ni0 = c0 ? pp : i0;
                    float nt1 = c0 ? t0 : (c1 ? vv : t1);
                    int   ni1 = c0 ? i0 : (c1 ? pp : i1);
                    float nt2 = c1 ? t1 : (c2 ? vv : t2);
                    int   ni2 = c1 ? i1 : (c2 ? pp : i2);
                    float nt3 = c2 ? t2 : vv;           int ni3 = c2 ? i2 : pp;
                    t0 = nt0; t1 = nt1; t2 = nt2; t3 = nt3;
                    i0 = ni0; i1 = ni1; i2 = ni2; i3 = ni3;
                }
            }
        }
        ipp += U * C;
        opp += U * C;
        pbase += U;
    }

    // candidate exchange: [seg][rank][col] -> conflict-free both phases
    __shared__ float sv[SEG][4][COLS];
    __shared__ int   si[SEG][4][COLS];
    sv[seg][0][lane] = t0; si[seg][0][lane] = i0;
    sv[seg][1][lane] = t1; si[seg][1][lane] = i1;
    sv[seg][2][lane] = t2; si[seg][2][lane] = i2;
    sv[seg][3][lane] = t3; si[seg][3][lane] = i3;

    __syncthreads();   // also orders this block's copy-stores before the patch

    if (tid < COLS) {
        const int pcol = blockIdx.x * COLS + tid;
        const int ps   = pcol / C;
        const int pc   = pcol - ps * C;
        float* opc = out + (size_t)ps * P * C + pc;

        float m0 = -CUDART_INF_F, m1 = -CUDART_INF_F,
              m2 = -CUDART_INF_F, m3 = -CUDART_INF_F;
        int   j0 = 0x7fffffff, j1 = 0x7fffffff,
              j2 = 0x7fffffff, j3 = 0x7fffffff;
        #pragma unroll
        for (int sg = 0; sg < SEG; sg++) {
            #pragma unroll
            for (int k = 0; k < 4; k++) {
                float v = sv[sg][k][tid];
                int   i = si[sg][k][tid];
                if (v > m3 || (v == m3 && i < j3)) {
                    if (v > m0 || (v == m0 && i < j0)) {
                        m3 = m2; j3 = j2; m2 = m1; j2 = j1; m1 = m0; j1 = j0;
                        m0 = v;  j0 = i;
                    } else if (v > m1 || (v == m1 && i < j1)) {
                        m3 = m2; j3 = j2; m2 = m1; j2 = j1;
                        m1 = v;  j1 = i;
                    } else if (v > m2 || (v == m2 && i < j2)) {
                        m3 = m2; j3 = j2;
                        m2 = v;  j2 = i;
                    } else {
                        m3 = v;  j3 = i;
                    }
                }
            }
        }
        opc[(size_t)j0 * C] = 0.0f;
        opc[(size_t)j1 * C] = 0.0f;
        opc[(size_t)j2 * C] = 0.0f;
        opc[(size_t)j3 * C] = 0.0f;
    }
}

extern "C" void kernel_launch(void* const* d_in, const int* in_sizes, int n_in,
                              void* d_out, int out_size) {
    (void)in_sizes; (void)n_in; (void)out_size;
    const float* in  = (const float*)d_in[0];
    float*       out = (float*)d_out;
    numproto_topk_zero<<<GRID, BLK>>>(in, out);
}